// round 12
// baseline (speedup 1.0000x reference)
#include <cuda_runtime.h>
#include <math.h>

// ----- problem dims -----
#define B_    32
#define T_    100
#define NN_   32
#define F_    8
#define D_    256
#define LH    512
#define G4    2048      // 4*LH
#define ROWS  3200      // B_*T_  (row = t*32 + b)
#define NBLK  128       // persistent LSTM grid

typedef unsigned long long ull;

// ----- device scratch -----
__device__ float d_G   [ROWS * D_];
__device__ float d_Pk  [4 * G4 * D_]; // split-K partials (covers lin1's 2x819200 too)
__device__ float d_F1  [G4 * D_];     // w_ih @ Wop
__device__ float d_Wbig[G4 * D_];     // w_ih @ Wop @ Wv
__device__ float d_batt[D_];          // Wop@bv + bop
__device__ float d_bihh[G4];          // w_ih@batt + b_ih + b_hh
__device__ float d_XT  [G4 * ROWS];   // X^T: [gate*512+j][t*32+b]
// hidden state, float4-grouped k-major: element (j,b) at (j>>2)*128 + b*4 + (j&3)
__device__ float d_hbuf[2][B_ * LH];
__device__ float d_LT  [LH * ROWS];   // L^T: [j][t*32+b]
__device__ float d_H1  [ROWS * D_];
__device__ int   d_bar;               // central barrier counter

__device__ __forceinline__ void ffma2(ull& d, ull a, ull b) {
    asm("fma.rn.f32x2 %0, %1, %2, %0;" : "+l"(d) : "l"(a), "l"(b));
}
__device__ __forceinline__ float tanh_fast(float x) {
    float ax = fabsf(x);
    float e  = __expf(-2.0f * ax);
    float t  = __fdividef(1.0f - e, 1.0f + e);
    return copysignf(t, x);
}
__device__ __forceinline__ float sigm(float x) {
    return 1.0f / (1.0f + __expf(-x));
}
__device__ __forceinline__ void red_release_add(int* p, int v) {
    asm volatile("red.release.gpu.global.add.s32 [%0], %1;" :: "l"(p), "r"(v) : "memory");
}
__device__ __forceinline__ int ld_acq(const int* p) {
    int v;
    asm volatile("ld.acquire.gpu.global.b32 %0, [%1];" : "=r"(v) : "l"(p) : "memory");
    return v;
}

// ======================================================================
// k_init: G = relu(mean_n(traj) @ gcn_w + gcn_b); also zero h[0], bar
// ======================================================================
__global__ void k_init(const float* __restrict__ traj,
                       const float* __restrict__ gw,
                       const float* __restrict__ gb) {
    int row = blockIdx.x;
    int t = row >> 5, b = row & 31;
    __shared__ float s[NN_ * F_];
    __shared__ float m[F_];
    int tid = threadIdx.x;

    if (row < 64) d_hbuf[0][row * 256 + tid] = 0.0f;
    if (row == 0 && tid == 0) d_bar = 0;

    const float* p = traj + (size_t)((b * T_ + t) * NN_) * F_;
    s[tid] = p[tid];
    __syncthreads();
    if (tid < F_) {
        float acc = 0.0f;
        #pragma unroll
        for (int n = 0; n < NN_; n++) acc += s[n * F_ + tid];
        m[tid] = acc * (1.0f / 32.0f);
    }
    __syncthreads();
    float acc = gb[tid];
    #pragma unroll
    for (int f = 0; f < F_; f++) acc += m[f] * gw[f * D_ + tid];
    d_G[(size_t)row * D_ + tid] = fmaxf(acc, 0.0f);
}

// ======================================================================
// GEMV (warp-per-row): out[j] = dot(W[j,:K], x) + add1[j] (+ add2[j])
// ======================================================================
__global__ void k_gemv(const float* __restrict__ W, int K,
                       const float* __restrict__ x,
                       const float* __restrict__ add1,
                       const float* __restrict__ add2,
                       float* __restrict__ out, int M) {
    int gw   = (blockIdx.x * blockDim.x + threadIdx.x) >> 5;
    int lane = threadIdx.x & 31;
    if (gw >= M) return;
    float s = 0.0f;
    for (int k = lane; k < K; k += 32)
        s += W[(size_t)gw * K + k] * x[k];
    #pragma unroll
    for (int off = 16; off > 0; off >>= 1)
        s += __shfl_xor_sync(0xffffffff, s, off);
    if (lane == 0) {
        float r = s + add1[gw];
        if (add2) r += add2[gw];
        out[gw] = r;
    }
}

// ======================================================================
// k_addn: C[i] = sum_{p<nparts} P[p*len4 + i]   (float4 elements)
// ======================================================================
__global__ void k_addn(const float* __restrict__ P, float* __restrict__ C,
                       int len4, int nparts) {
    int i = blockIdx.x * blockDim.x + threadIdx.x;
    if (i < len4) {
        float4 v = ((const float4*)P)[i];
        for (int p = 1; p < nparts; p++) {
            float4 a = ((const float4*)P)[(size_t)p * len4 + i];
            v.x += a.x; v.y += a.y; v.z += a.z; v.w += a.w;
        }
        ((float4*)C)[i] = v;
    }
}

// ======================================================================
// k_addbr: C[i] = relu(P[i] + P[len4+i] + bias) ; bias per output col,
// row length N floats (N/4 float4)
// ======================================================================
__global__ void k_addbr(const float* __restrict__ P, const float* __restrict__ bias,
                        float* __restrict__ C, int len4, int n4) {
    int i = blockIdx.x * blockDim.x + threadIdx.x;
    if (i < len4) {
        float4 a = ((const float4*)P)[i];
        float4 b = ((const float4*)P)[len4 + i];
        float4 bi = ((const float4*)bias)[i % n4];
        float4 v;
        v.x = fmaxf(a.x + b.x + bi.x, 0.0f);
        v.y = fmaxf(a.y + b.y + bi.y, 0.0f);
        v.z = fmaxf(a.z + b.z + bi.z, 0.0f);
        v.w = fmaxf(a.w + b.w + bi.w, 0.0f);
        ((float4*)C)[i] = v;
    }
}

// ======================================================================
// SGEMM-NT (proven, occ 2): C[M,N] = A[M,K] @ B[N,K]^T + biasM[m]
// BM=BN=128, BK=16, 256 threads, 8x8 micro-tile.
// ======================================================================
__global__ void __launch_bounds__(256)
sgemm_nt_bm(const float* __restrict__ A, const float* __restrict__ Bm,
            const float* __restrict__ biasM, float* __restrict__ C,
            int M, int N, int K) {
    __shared__ __align__(16) float As[16][128];
    __shared__ __align__(16) float Bs[16][128];

    int tid = threadIdx.x;
    int m0 = blockIdx.y * 128, n0 = blockIdx.x * 128;
    int tm = (tid >> 4) * 8, tn = (tid & 15) * 8;

    float acc[8][8];
    #pragma unroll
    for (int i = 0; i < 8; i++)
        #pragma unroll
        for (int j = 0; j < 8; j++) acc[i][j] = 0.0f;

    for (int k0 = 0; k0 < K; k0 += 16) {
        #pragma unroll
        for (int i = 0; i < 2; i++) {
            int idx = tid + i * 256;
            int r  = idx >> 2;
            int kq = (idx & 3) * 4;
            float4 va = *(const float4*)&A [(size_t)(m0 + r) * K + k0 + kq];
            As[kq + 0][r] = va.x; As[kq + 1][r] = va.y;
            As[kq + 2][r] = va.z; As[kq + 3][r] = va.w;
            float4 vb = *(const float4*)&Bm[(size_t)(n0 + r) * K + k0 + kq];
            Bs[kq + 0][r] = vb.x; Bs[kq + 1][r] = vb.y;
            Bs[kq + 2][r] = vb.z; Bs[kq + 3][r] = vb.w;
        }
        __syncthreads();
        #pragma unroll
        for (int kk = 0; kk < 16; kk++) {
            float a[8], b[8];
            *(float4*)&a[0] = *(const float4*)&As[kk][tm];
            *(float4*)&a[4] = *(const float4*)&As[kk][tm + 4];
            *(float4*)&b[0] = *(const float4*)&Bs[kk][tn];
            *(float4*)&b[4] = *(const float4*)&Bs[kk][tn + 4];
            #pragma unroll
            for (int i = 0; i < 8; i++)
                #pragma unroll
                for (int j = 0; j < 8; j++)
                    acc[i][j] += a[i] * b[j];
        }
        __syncthreads();
    }

    #pragma unroll
    for (int i = 0; i < 8; i++) {
        float bm = biasM[m0 + tm + i];
        float* crow = C + (size_t)(m0 + tm + i) * N;
        #pragma unroll
        for (int j = 0; j < 8; j += 4) {
            float4 v;
            v.x = acc[i][j + 0] + bm; v.y = acc[i][j + 1] + bm;
            v.z = acc[i][j + 2] + bm; v.w = acc[i][j + 3] + bm;
            *(float4*)&crow[n0 + tn + j] = v;
        }
    }
}

// ======================================================================
// SGEMM BM=64 BN=128 BK=16, 256 threads, 4x8 micro-tile.
// flags: 1=relu, 2=permute rows, 4=NN (B is W[K,N], ld ldb), 8=no bias,
//        16=TN (A is AT[K][M], ld lda), 32=split-K (part z: A+=z*kadvA,
//        B+=z*kadvB, C+=z*M*N)
// ======================================================================
__global__ void __launch_bounds__(256)
sgemm64b(const float* __restrict__ A, const float* __restrict__ Bm,
         const float* __restrict__ bias, float* __restrict__ C,
         int M, int N, int K, int flags, int lda, int ldb,
         size_t kadvA, size_t kadvB) {
    __shared__ __align__(16) float As[16][64];
    __shared__ __align__(16) float Bs[16][128];

    int tid = threadIdx.x;
    int m0 = blockIdx.y * 64, n0 = blockIdx.x * 128;
    int tm = (tid >> 4) * 4, tn = (tid & 15) * 8;

    if (flags & 32) {
        A  += blockIdx.z * kadvA;
        Bm += blockIdx.z * kadvB;
        C  += (size_t)blockIdx.z * M * N;
    }

    float acc[4][8];
    #pragma unroll
    for (int i = 0; i < 4; i++)
        #pragma unroll
        for (int j = 0; j < 8; j++) acc[i][j] = 0.0f;

    for (int k0 = 0; k0 < K; k0 += 16) {
        if (flags & 16) {  // TN: A is AT[k][m], ld lda
            int kk = tid >> 4;
            int c  = (tid & 15) * 4;
            float4 va = *(const float4*)&A[(size_t)(k0 + kk) * lda + m0 + c];
            *(float4*)&As[kk][c] = va;
        } else {           // A row-major [m][k], ld lda
            int r  = tid >> 2;
            int kq = (tid & 3) * 4;
            float4 va = *(const float4*)&A[(size_t)(m0 + r) * lda + k0 + kq];
            As[kq + 0][r] = va.x; As[kq + 1][r] = va.y;
            As[kq + 2][r] = va.z; As[kq + 3][r] = va.w;
        }
        if (flags & 4) {   // NN: W[k][n], ld ldb
            #pragma unroll
            for (int i = 0; i < 2; i++) {
                int idx = tid + i * 256;
                int kk = idx >> 5;
                int c  = (idx & 31) * 4;
                float4 vb = *(const float4*)&Bm[(size_t)(k0 + kk) * ldb + n0 + c];
                *(float4*)&Bs[kk][c] = vb;
            }
        } else {           // NT: B[n][k], ld ldb
            #pragma unroll
            for (int i = 0; i < 2; i++) {
                int idx = tid + i * 256;
                int r  = idx >> 2;
                int kq = (idx & 3) * 4;
                float4 vb = *(const float4*)&Bm[(size_t)(n0 + r) * ldb + k0 + kq];
                Bs[kq + 0][r] = vb.x; Bs[kq + 1][r] = vb.y;
                Bs[kq + 2][r] = vb.z; Bs[kq + 3][r] = vb.w;
            }
        }
        __syncthreads();
        #pragma unroll
        for (int kk = 0; kk < 16; kk++) {
            float a[4], b[8];
            *(float4*)&a[0] = *(const float4*)&As[kk][tm];
            *(float4*)&b[0] = *(const float4*)&Bs[kk][tn];
            *(float4*)&b[4] = *(const float4*)&Bs[kk][tn + 4];
            #pragma unroll
            for (int i = 0; i < 4; i++)
                #pragma unroll
                for (int j = 0; j < 8; j++)
                    acc[i][j] += a[i] * b[j];
        }
        __syncthreads();
    }

    #pragma unroll
    for (int i = 0; i < 4; i++) {
        int m = m0 + tm + i;
        float* crow;
        if (flags & 2) { int b = m & 31, tt = m >> 5; crow = C + (size_t)(b * T_ + tt) * N; }
        else           { crow = C + (size_t)m * N; }
        #pragma unroll
        for (int j = 0; j < 8; j += 4) {
            float4 v;
            v.x = acc[i][j + 0]; v.y = acc[i][j + 1];
            v.z = acc[i][j + 2]; v.w = acc[i][j + 3];
            if (!(flags & 8)) {
                v.x += bias[n0 + tn + j + 0]; v.y += bias[n0 + tn + j + 1];
                v.z += bias[n0 + tn + j + 2]; v.w += bias[n0 + tn + j + 3];
            }
            if (flags & 1) {
                v.x = fmaxf(v.x, 0.0f); v.y = fmaxf(v.y, 0.0f);
                v.z = fmaxf(v.z, 0.0f); v.w = fmaxf(v.w, 0.0f);
            }
            *(float4*)&crow[n0 + tn + j] = v;
        }
    }
}

// ======================================================================
// Persistent LSTM: 128 blocks x 256 threads; depth-4 h-load pipeline.
// ======================================================================
#define SM_WS4   0
#define SM_PACC  (SM_WS4 + 16 * 128 * 16)
#define SM_CS    (SM_PACC + 8 * 16 * 32 * 4)
#define SM_TOTAL (SM_CS + 128 * 4)

__global__ void __launch_bounds__(256, 1)
k_lstm(const float* __restrict__ whh) {
    extern __shared__ char smem[];
    float4* ws4  = (float4*)(smem + SM_WS4);   // [r][q]  r=gate*4+jj
    float*  pacc = (float*) (smem + SM_PACC);  // [w][r][b]
    float*  cs   = (float*) (smem + SM_CS);    // [jj][b]

    int tid = threadIdx.x, lane = tid & 31, wrp = tid >> 5;
    int j0 = blockIdx.x * 4;

    #pragma unroll
    for (int i = 0; i < 8; i++) {
        int idx = i * 256 + tid;
        int r = idx >> 7, q = idx & 127;
        int rr = (r >> 2) * LH + j0 + (r & 3);
        ws4[r * 128 + q] = ((const float4*)whh)[(size_t)rr * 128 + q];
    }
    if (tid < 128) cs[tid] = 0.0f;
    __syncthreads();

    const int qbase = wrp * 16;
    const int pjj = tid >> 5;
    const int pb  = tid & 31;
    const size_t xbase = (size_t)(j0 + pjj) * ROWS + pb;
    const size_t gstr  = (size_t)LH * ROWS;

    float xg0 = 0, xg1 = 0, xg2 = 0, xg3 = 0;
    if (tid < 128) {
        xg0 = __ldcg(&d_XT[xbase + 0 * gstr]);
        xg1 = __ldcg(&d_XT[xbase + 1 * gstr]);
        xg2 = __ldcg(&d_XT[xbase + 2 * gstr]);
        xg3 = __ldcg(&d_XT[xbase + 3 * gstr]);
    }

    for (int t = 0; t < T_; t++) {
        const float4* hin = (const float4*)d_hbuf[t & 1];

        float xn0 = 0, xn1 = 0, xn2 = 0, xn3 = 0;
        if (tid < 128 && t + 1 < T_) {
            size_t o = xbase + (t + 1) * 32;
            xn0 = __ldcg(&d_XT[o + 0 * gstr]);
            xn1 = __ldcg(&d_XT[o + 1 * gstr]);
            xn2 = __ldcg(&d_XT[o + 2 * gstr]);
            xn3 = __ldcg(&d_XT[o + 3 * gstr]);
        }

        // depth-4 pipelined h loads over the 16-q slice
        float4 hq[4];
        #pragma unroll
        for (int i = 0; i < 4; i++)
            hq[i] = __ldcg(&hin[(qbase + i) * 32 + lane]);

        ull alo[16], ahi[16];
        #pragma unroll
        for (int r = 0; r < 16; r++) { alo[r] = 0ULL; ahi[r] = 0ULL; }

        #pragma unroll
        for (int qq = 0; qq < 16; qq++) {
            float4 hv = hq[qq & 3];
            if (qq < 12)
                hq[qq & 3] = __ldcg(&hin[(qbase + qq + 4) * 32 + lane]);
            ull hlo = ((ull*)&hv)[0], hhi = ((ull*)&hv)[1];
            #pragma unroll
            for (int r = 0; r < 16; r++) {
                float4 wv = ws4[r * 128 + qbase + qq];
                ffma2(alo[r], ((ull*)&wv)[0], hlo);
                ffma2(ahi[r], ((ull*)&wv)[1], hhi);
            }
        }
        #pragma unroll
        for (int r = 0; r < 16; r++) {
            float2 a = *(float2*)&alo[r], b = *(float2*)&ahi[r];
            pacc[(wrp * 16 + r) * 32 + lane] = a.x + a.y + b.x + b.y;
        }
        __syncthreads();

        if (tid < 128) {
            float zi = xg0, zf = xg1, zg = xg2, zo = xg3;
            #pragma unroll
            for (int w = 0; w < 8; w++) {
                const float* pw = pacc + (w * 16) * 32 + pb;
                zi += pw[( 0 + pjj) * 32];
                zf += pw[( 4 + pjj) * 32];
                zg += pw[( 8 + pjj) * 32];
                zo += pw[(12 + pjj) * 32];
            }
            float cp = cs[pjj * 32 + pb];
            float ig = sigm(zi), fg = sigm(zf);
            float gg = tanh_fast(zg), og = sigm(zo);
            float cn = fg * cp + ig * gg;
            float hn = og * tanh_fast(cn);
            cs[pjj * 32 + pb] = cn;
            d_hbuf[(t + 1) & 1][blockIdx.x * 128 + pb * 4 + pjj] = hn;
            d_LT[(size_t)(j0 + pjj) * ROWS + t * 32 + pb] = hn;
        }
        xg0 = xn0; xg1 = xn1; xg2 = xn2; xg3 = xn3;

        __syncthreads();
        if (tid == 0) {
            red_release_add(&d_bar, 1);
            while (ld_acq(&d_bar) < NBLK * (t + 1)) { }
        }
        __syncthreads();
    }
}

// ======================================================================
extern "C" void kernel_launch(void* const* d_in, const int* in_sizes, int n_in,
                              void* d_out, int out_size) {
    const float* traj      = (const float*)d_in[0];
    const float* gcn_w     = (const float*)d_in[1];
    const float* gcn_b     = (const float*)d_in[2];
    const float* in_proj_w = (const float*)d_in[3];
    const float* in_proj_b = (const float*)d_in[4];
    const float* out_proj_w= (const float*)d_in[5];
    const float* out_proj_b= (const float*)d_in[6];
    // d_in[7]=va_w, d_in[8]=va_b : unused (uniform softmaxes)
    const float* w_ih      = (const float*)d_in[9];
    const float* w_hh      = (const float*)d_in[10];
    const float* b_ih      = (const float*)d_in[11];
    const float* b_hh      = (const float*)d_in[12];
    const float* lin1_w    = (const float*)d_in[13];
    const float* lin1_b    = (const float*)d_in[14];
    const float* lin2_w    = (const float*)d_in[15];
    const float* lin2_b    = (const float*)d_in[16];
    float* out = (float*)d_out;

    float *pG, *pPk, *pF1, *pWbig, *pbatt, *pbihh, *pXT, *pLT, *pH1;
    cudaGetSymbolAddress((void**)&pG,    d_G);
    cudaGetSymbolAddress((void**)&pPk,   d_Pk);
    cudaGetSymbolAddress((void**)&pF1,   d_F1);
    cudaGetSymbolAddress((void**)&pWbig, d_Wbig);
    cudaGetSymbolAddress((void**)&pbatt, d_batt);
    cudaGetSymbolAddress((void**)&pbihh, d_bihh);
    cudaGetSymbolAddress((void**)&pXT,   d_XT);
    cudaGetSymbolAddress((void**)&pLT,   d_LT);
    cudaGetSymbolAddress((void**)&pH1,   d_H1);

    static int smem_set = 0;
    if (!smem_set) {
        cudaFuncSetAttribute(k_lstm, cudaFuncAttributeMaxDynamicSharedMemorySize,
                             SM_TOTAL);
        smem_set = 1;
    }

    const float* bv = in_proj_b + 2 * D_;
    const float* Wv = in_proj_w + (size_t)2 * D_ * D_;
    const int KQ = D_ / 4;                // 64 per split-K=4 part

    k_init<<<ROWS, 256>>>(traj, gcn_w, gcn_b);

    // bias chain (parallel gemvs)
    k_gemv<<<32, 256>>>(out_proj_w, D_, bv, out_proj_b, nullptr, pbatt, D_);
    k_gemv<<<256, 256>>>(w_ih, D_, pbatt, b_ih, b_hh, pbihh, G4);

    // F1 = w_ih @ Wop  (NN split-K=4)
    sgemm64b<<<dim3(D_ / 128, G4 / 64, 4), 256>>>(
        w_ih, out_proj_w, nullptr, pPk, G4, D_, KQ, 4 | 8 | 32,
        D_, D_, (size_t)KQ, (size_t)KQ * D_);
    k_addn<<<(G4 * D_ / 4 + 255) / 256, 256>>>(pPk, pF1, G4 * D_ / 4, 4);

    // Wbig = F1 @ Wv   (NN split-K=4)
    sgemm64b<<<dim3(D_ / 128, G4 / 64, 4), 256>>>(
        pF1, Wv, nullptr, pPk, G4, D_, KQ, 4 | 8 | 32,
        D_, D_, (size_t)KQ, (size_t)KQ * D_);
    k_addn<<<(G4 * D_ / 4 + 255) / 256, 256>>>(pPk, pWbig, G4 * D_ / 4, 4);

    // XT = Wbig @ G^T + bias_x[m]
    sgemm_nt_bm<<<dim3(ROWS / 128, G4 / 128), 256>>>(
        pWbig, pG, pbihh, pXT, G4, ROWS, D_);

    // persistent LSTM
    k_lstm<<<NBLK, 256, SM_TOTAL>>>(w_hh);

    // lin1 split-K=2: partials (TN, no bias/relu), then fused add+bias+relu
    sgemm64b<<<dim3(D_ / 128, ROWS / 64, 2), 256>>>(
        pLT, lin1_w, nullptr, pPk, ROWS, D_, LH / 2, 8 | 16 | 32,
        ROWS, LH, (size_t)(LH / 2) * ROWS, (size_t)(LH / 2));
    k_addbr<<<(ROWS * D_ / 4 + 255) / 256, 256>>>(
        pPk, lin1_b, pH1, ROWS * D_ / 4, D_ / 4);

    // out = H1 @ lin2_w^T + b, permuted store
    sgemm64b<<<dim3(128 / 128, ROWS / 64), 256>>>(
        pH1, lin2_w, lin2_b, out, ROWS, 128, D_, 2,
        D_, D_, 0, 0);
}

// round 13
// speedup vs baseline: 1.0627x; 1.0627x over previous
#include <cuda_runtime.h>
#include <math.h>

// ----- problem dims -----
#define B_    32
#define T_    100
#define NN_   32
#define F_    8
#define D_    256
#define LH    512
#define G4    2048      // 4*LH
#define ROWS  3200      // B_*T_  (row = t*32 + b)
#define NBLK  128       // persistent LSTM grid

typedef unsigned long long ull;
typedef unsigned int uint;

// ----- device scratch -----
__device__ float d_G   [ROWS * D_];
__device__ float d_Pk  [4 * G4 * D_]; // split-K partials
__device__ float d_F1  [G4 * D_];     // w_ih @ Wop
__device__ float d_Wbig[G4 * D_];     // w_ih @ Wop @ Wv
__device__ float d_batt[D_];          // Wop@bv + bop
__device__ float d_bihh[G4];          // w_ih@batt + b_ih + b_hh
__device__ float d_XT  [G4 * ROWS];   // X^T: [gate*512+j][t*32+b]
__device__ float d_hbuf[2][B_ * LH];  // float4-grouped k-major
__device__ float d_LT  [LH * ROWS];   // L^T: [j][t*32+b]
__device__ float d_H1  [ROWS * D_];
__device__ int   d_bar;               // central barrier counter

__device__ __forceinline__ void ffma2(ull& d, ull a, ull b) {
    asm("fma.rn.f32x2 %0, %1, %2, %0;" : "+l"(d) : "l"(a), "l"(b));
}
__device__ __forceinline__ uint f2tf32(float x) {
    uint r;
    asm("cvt.rna.tf32.f32 %0, %1;" : "=r"(r) : "f"(x));
    return r;
}
__device__ __forceinline__ float tanh_fast(float x) {
    float ax = fabsf(x);
    float e  = __expf(-2.0f * ax);
    float t  = __fdividef(1.0f - e, 1.0f + e);
    return copysignf(t, x);
}
__device__ __forceinline__ float sigm(float x) {
    return 1.0f / (1.0f + __expf(-x));
}
__device__ __forceinline__ void red_release_add(int* p, int v) {
    asm volatile("red.release.gpu.global.add.s32 [%0], %1;" :: "l"(p), "r"(v) : "memory");
}
__device__ __forceinline__ int ld_acq(const int* p) {
    int v;
    asm volatile("ld.acquire.gpu.global.b32 %0, [%1];" : "=r"(v) : "l"(p) : "memory");
    return v;
}

// ======================================================================
// k_init: G = relu(mean_n(traj) @ gcn_w + gcn_b); also zero h[0], bar
// ======================================================================
__global__ void k_init(const float* __restrict__ traj,
                       const float* __restrict__ gw,
                       const float* __restrict__ gb) {
    int row = blockIdx.x;
    int t = row >> 5, b = row & 31;
    __shared__ float s[NN_ * F_];
    __shared__ float m[F_];
    int tid = threadIdx.x;

    if (row < 64) d_hbuf[0][row * 256 + tid] = 0.0f;
    if (row == 0 && tid == 0) d_bar = 0;

    const float* p = traj + (size_t)((b * T_ + t) * NN_) * F_;
    s[tid] = p[tid];
    __syncthreads();
    if (tid < F_) {
        float acc = 0.0f;
        #pragma unroll
        for (int n = 0; n < NN_; n++) acc += s[n * F_ + tid];
        m[tid] = acc * (1.0f / 32.0f);
    }
    __syncthreads();
    float acc = gb[tid];
    #pragma unroll
    for (int f = 0; f < F_; f++) acc += m[f] * gw[f * D_ + tid];
    d_G[(size_t)row * D_ + tid] = fmaxf(acc, 0.0f);
}

// ======================================================================
// GEMV (warp-per-row)
// ======================================================================
__global__ void k_gemv(const float* __restrict__ W, int K,
                       const float* __restrict__ x,
                       const float* __restrict__ add1,
                       const float* __restrict__ add2,
                       float* __restrict__ out, int M) {
    int gw   = (blockIdx.x * blockDim.x + threadIdx.x) >> 5;
    int lane = threadIdx.x & 31;
    if (gw >= M) return;
    float s = 0.0f;
    for (int k = lane; k < K; k += 32)
        s += W[(size_t)gw * K + k] * x[k];
    #pragma unroll
    for (int off = 16; off > 0; off >>= 1)
        s += __shfl_xor_sync(0xffffffff, s, off);
    if (lane == 0) {
        float r = s + add1[gw];
        if (add2) r += add2[gw];
        out[gw] = r;
    }
}

// ======================================================================
// k_addn: C[i] = sum_{p<nparts} P[p*len4 + i]   (float4 elements)
// ======================================================================
__global__ void k_addn(const float* __restrict__ P, float* __restrict__ C,
                       int len4, int nparts) {
    int i = blockIdx.x * blockDim.x + threadIdx.x;
    if (i < len4) {
        float4 v = ((const float4*)P)[i];
        for (int p = 1; p < nparts; p++) {
            float4 a = ((const float4*)P)[(size_t)p * len4 + i];
            v.x += a.x; v.y += a.y; v.z += a.z; v.w += a.w;
        }
        ((float4*)C)[i] = v;
    }
}

// ======================================================================
// TF32 SGEMM-NT: C[M,N] = A[M,K] @ B[N,K]^T + biasM[m]
// BM=BN=128, BK=32, 256 threads = 8 warps (2m x 4n), warp tile 64x32.
// mma.sync.m16n8k8 tf32, fp32 accumulate. Shared ld=36 -> conflict-free
// fragment loads (bank = (4*row + k) % 32 distinct across the warp).
// ======================================================================
__global__ void __launch_bounds__(256)
sgemm_nt_tf32(const float* __restrict__ A, const float* __restrict__ Bm,
              const float* __restrict__ biasM, float* __restrict__ C,
              int M, int N, int K) {
    __shared__ uint As[128][36];
    __shared__ uint Bs[128][36];

    int tid = threadIdx.x, lane = tid & 31, wid = tid >> 5;
    int g = lane >> 2, t = lane & 3;
    int warp_m = wid >> 2, warp_n = wid & 3;
    int m0 = blockIdx.y * 128, n0 = blockIdx.x * 128;

    float c[4][4][4];
    #pragma unroll
    for (int i = 0; i < 4; i++)
        #pragma unroll
        for (int j = 0; j < 4; j++)
            #pragma unroll
            for (int e = 0; e < 4; e++) c[i][j][e] = 0.0f;

    for (int k0 = 0; k0 < K; k0 += 32) {
        #pragma unroll
        for (int i = 0; i < 4; i++) {
            int idx = tid + i * 256;          // 0..1023
            int r  = idx >> 3;                // 0..127
            int kq = (idx & 7) * 4;           // 0..28
            float4 va = *(const float4*)&A [(size_t)(m0 + r) * K + k0 + kq];
            As[r][kq + 0] = f2tf32(va.x); As[r][kq + 1] = f2tf32(va.y);
            As[r][kq + 2] = f2tf32(va.z); As[r][kq + 3] = f2tf32(va.w);
            float4 vb = *(const float4*)&Bm[(size_t)(n0 + r) * K + k0 + kq];
            Bs[r][kq + 0] = f2tf32(vb.x); Bs[r][kq + 1] = f2tf32(vb.y);
            Bs[r][kq + 2] = f2tf32(vb.z); Bs[r][kq + 3] = f2tf32(vb.w);
        }
        __syncthreads();
        #pragma unroll
        for (int kb = 0; kb < 32; kb += 8) {
            uint bfr[4][2];
            #pragma unroll
            for (int nf = 0; nf < 4; nf++) {
                int n = warp_n * 32 + nf * 8 + g;
                bfr[nf][0] = Bs[n][kb + t];
                bfr[nf][1] = Bs[n][kb + t + 4];
            }
            #pragma unroll
            for (int mf = 0; mf < 4; mf++) {
                int m = warp_m * 64 + mf * 16 + g;
                uint a0 = As[m    ][kb + t    ];
                uint a1 = As[m + 8][kb + t    ];
                uint a2 = As[m    ][kb + t + 4];
                uint a3 = As[m + 8][kb + t + 4];
                #pragma unroll
                for (int nf = 0; nf < 4; nf++) {
                    asm volatile(
                        "mma.sync.aligned.m16n8k8.row.col.f32.tf32.tf32.f32 "
                        "{%0,%1,%2,%3}, {%4,%5,%6,%7}, {%8,%9}, {%0,%1,%2,%3};"
                        : "+f"(c[mf][nf][0]), "+f"(c[mf][nf][1]),
                          "+f"(c[mf][nf][2]), "+f"(c[mf][nf][3])
                        : "r"(a0), "r"(a1), "r"(a2), "r"(a3),
                          "r"(bfr[nf][0]), "r"(bfr[nf][1]));
                }
            }
        }
        __syncthreads();
    }

    // epilogue: c[mf][nf] -> rows (mg, mg+8), cols (ng, ng+1)
    #pragma unroll
    for (int mf = 0; mf < 4; mf++) {
        int mg = m0 + warp_m * 64 + mf * 16 + g;
        float b0v = biasM[mg], b1v = biasM[mg + 8];
        #pragma unroll
        for (int nf = 0; nf < 4; nf++) {
            int ng = n0 + warp_n * 32 + nf * 8 + t * 2;
            float2 v0 = make_float2(c[mf][nf][0] + b0v, c[mf][nf][1] + b0v);
            float2 v1 = make_float2(c[mf][nf][2] + b1v, c[mf][nf][3] + b1v);
            *(float2*)&C[(size_t)mg * N + ng]       = v0;
            *(float2*)&C[(size_t)(mg + 8) * N + ng] = v1;
        }
    }
}

// ======================================================================
// SGEMM BM=64 BN=128 BK=16, 256 threads, 4x8 micro-tile.
// flags: 1=relu, 2=permute rows, 4=NN (B is W[K,N], ld ldb), 8=no bias,
//        16=TN (A is AT[K][M], ld lda), 32=split-K
// ======================================================================
__global__ void __launch_bounds__(256)
sgemm64b(const float* __restrict__ A, const float* __restrict__ Bm,
         const float* __restrict__ bias, float* __restrict__ C,
         int M, int N, int K, int flags, int lda, int ldb,
         size_t kadvA, size_t kadvB) {
    __shared__ __align__(16) float As[16][64];
    __shared__ __align__(16) float Bs[16][128];

    int tid = threadIdx.x;
    int m0 = blockIdx.y * 64, n0 = blockIdx.x * 128;
    int tm = (tid >> 4) * 4, tn = (tid & 15) * 8;

    if (flags & 32) {
        A  += blockIdx.z * kadvA;
        Bm += blockIdx.z * kadvB;
        C  += (size_t)blockIdx.z * M * N;
    }

    float acc[4][8];
    #pragma unroll
    for (int i = 0; i < 4; i++)
        #pragma unroll
        for (int j = 0; j < 8; j++) acc[i][j] = 0.0f;

    for (int k0 = 0; k0 < K; k0 += 16) {
        if (flags & 16) {
            int kk = tid >> 4;
            int c  = (tid & 15) * 4;
            float4 va = *(const float4*)&A[(size_t)(k0 + kk) * lda + m0 + c];
            *(float4*)&As[kk][c] = va;
        } else {
            int r  = tid >> 2;
            int kq = (tid & 3) * 4;
            float4 va = *(const float4*)&A[(size_t)(m0 + r) * lda + k0 + kq];
            As[kq + 0][r] = va.x; As[kq + 1][r] = va.y;
            As[kq + 2][r] = va.z; As[kq + 3][r] = va.w;
        }
        if (flags & 4) {
            #pragma unroll
            for (int i = 0; i < 2; i++) {
                int idx = tid + i * 256;
                int kk = idx >> 5;
                int c  = (idx & 31) * 4;
                float4 vb = *(const float4*)&Bm[(size_t)(k0 + kk) * ldb + n0 + c];
                *(float4*)&Bs[kk][c] = vb;
            }
        } else {
            #pragma unroll
            for (int i = 0; i < 2; i++) {
                int idx = tid + i * 256;
                int r  = idx >> 2;
                int kq = (idx & 3) * 4;
                float4 vb = *(const float4*)&Bm[(size_t)(n0 + r) * ldb + k0 + kq];
                Bs[kq + 0][r] = vb.x; Bs[kq + 1][r] = vb.y;
                Bs[kq + 2][r] = vb.z; Bs[kq + 3][r] = vb.w;
            }
        }
        __syncthreads();
        #pragma unroll
        for (int kk = 0; kk < 16; kk++) {
            float a[4], b[8];
            *(float4*)&a[0] = *(const float4*)&As[kk][tm];
            *(float4*)&b[0] = *(const float4*)&Bs[kk][tn];
            *(float4*)&b[4] = *(const float4*)&Bs[kk][tn + 4];
            #pragma unroll
            for (int i = 0; i < 4; i++)
                #pragma unroll
                for (int j = 0; j < 8; j++)
                    acc[i][j] += a[i] * b[j];
        }
        __syncthreads();
    }

    #pragma unroll
    for (int i = 0; i < 4; i++) {
        int m = m0 + tm + i;
        float* crow;
        if (flags & 2) { int b = m & 31, tt = m >> 5; crow = C + (size_t)(b * T_ + tt) * N; }
        else           { crow = C + (size_t)m * N; }
        #pragma unroll
        for (int j = 0; j < 8; j += 4) {
            float4 v;
            v.x = acc[i][j + 0]; v.y = acc[i][j + 1];
            v.z = acc[i][j + 2]; v.w = acc[i][j + 3];
            if (!(flags & 8)) {
                v.x += bias[n0 + tn + j + 0]; v.y += bias[n0 + tn + j + 1];
                v.z += bias[n0 + tn + j + 2]; v.w += bias[n0 + tn + j + 3];
            }
            if (flags & 1) {
                v.x = fmaxf(v.x, 0.0f); v.y = fmaxf(v.y, 0.0f);
                v.z = fmaxf(v.z, 0.0f); v.w = fmaxf(v.w, 0.0f);
            }
            *(float4*)&crow[n0 + tn + j] = v;
        }
    }
}

// ======================================================================
// Persistent LSTM: 128 blocks x 256 threads; depth-4 h-load pipeline.
// ======================================================================
#define SM_WS4   0
#define SM_PACC  (SM_WS4 + 16 * 128 * 16)
#define SM_CS    (SM_PACC + 8 * 16 * 32 * 4)
#define SM_TOTAL (SM_CS + 128 * 4)

__global__ void __launch_bounds__(256, 1)
k_lstm(const float* __restrict__ whh) {
    extern __shared__ char smem[];
    float4* ws4  = (float4*)(smem + SM_WS4);
    float*  pacc = (float*) (smem + SM_PACC);
    float*  cs   = (float*) (smem + SM_CS);

    int tid = threadIdx.x, lane = tid & 31, wrp = tid >> 5;
    int j0 = blockIdx.x * 4;

    #pragma unroll
    for (int i = 0; i < 8; i++) {
        int idx = i * 256 + tid;
        int r = idx >> 7, q = idx & 127;
        int rr = (r >> 2) * LH + j0 + (r & 3);
        ws4[r * 128 + q] = ((const float4*)whh)[(size_t)rr * 128 + q];
    }
    if (tid < 128) cs[tid] = 0.0f;
    __syncthreads();

    const int qbase = wrp * 16;
    const int pjj = tid >> 5;
    const int pb  = tid & 31;
    const size_t xbase = (size_t)(j0 + pjj) * ROWS + pb;
    const size_t gstr  = (size_t)LH * ROWS;

    float xg0 = 0, xg1 = 0, xg2 = 0, xg3 = 0;
    if (tid < 128) {
        xg0 = __ldcg(&d_XT[xbase + 0 * gstr]);
        xg1 = __ldcg(&d_XT[xbase + 1 * gstr]);
        xg2 = __ldcg(&d_XT[xbase + 2 * gstr]);
        xg3 = __ldcg(&d_XT[xbase + 3 * gstr]);
    }

    for (int t = 0; t < T_; t++) {
        const float4* hin = (const float4*)d_hbuf[t & 1];

        float xn0 = 0, xn1 = 0, xn2 = 0, xn3 = 0;
        if (tid < 128 && t + 1 < T_) {
            size_t o = xbase + (t + 1) * 32;
            xn0 = __ldcg(&d_XT[o + 0 * gstr]);
            xn1 = __ldcg(&d_XT[o + 1 * gstr]);
            xn2 = __ldcg(&d_XT[o + 2 * gstr]);
            xn3 = __ldcg(&d_XT[o + 3 * gstr]);
        }

        float4 hq[4];
        #pragma unroll
        for (int i = 0; i < 4; i++)
            hq[i] = __ldcg(&hin[(qbase + i) * 32 + lane]);

        ull alo[16], ahi[16];
        #pragma unroll
        for (int r = 0; r < 16; r++) { alo[r] = 0ULL; ahi[r] = 0ULL; }

        #pragma unroll
        for (int qq = 0; qq < 16; qq++) {
            float4 hv = hq[qq & 3];
            if (qq < 12)
                hq[qq & 3] = __ldcg(&hin[(qbase + qq + 4) * 32 + lane]);
            ull hlo = ((ull*)&hv)[0], hhi = ((ull*)&hv)[1];
            #pragma unroll
            for (int r = 0; r < 16; r++) {
                float4 wv = ws4[r * 128 + qbase + qq];
                ffma2(alo[r], ((ull*)&wv)[0], hlo);
                ffma2(ahi[r], ((ull*)&wv)[1], hhi);
            }
        }
        #pragma unroll
        for (int r = 0; r < 16; r++) {
            float2 a = *(float2*)&alo[r], b = *(float2*)&ahi[r];
            pacc[(wrp * 16 + r) * 32 + lane] = a.x + a.y + b.x + b.y;
        }
        __syncthreads();

        if (tid < 128) {
            float zi = xg0, zf = xg1, zg = xg2, zo = xg3;
            #pragma unroll
            for (int w = 0; w < 8; w++) {
                const float* pw = pacc + (w * 16) * 32 + pb;
                zi += pw[( 0 + pjj) * 32];
                zf += pw[( 4 + pjj) * 32];
                zg += pw[( 8 + pjj) * 32];
                zo += pw[(12 + pjj) * 32];
            }
            float cp = cs[pjj * 32 + pb];
            float ig = sigm(zi), fg = sigm(zf);
            float gg = tanh_fast(zg), og = sigm(zo);
            float cn = fg * cp + ig * gg;
            float hn = og * tanh_fast(cn);
            cs[pjj * 32 + pb] = cn;
            d_hbuf[(t + 1) & 1][blockIdx.x * 128 + pb * 4 + pjj] = hn;
            d_LT[(size_t)(j0 + pjj) * ROWS + t * 32 + pb] = hn;
        }
        xg0 = xn0; xg1 = xn1; xg2 = xn2; xg3 = xn3;

        __syncthreads();
        if (tid == 0) {
            red_release_add(&d_bar, 1);
            while (ld_acq(&d_bar) < NBLK * (t + 1)) { }
        }
        __syncthreads();
    }
}

// ======================================================================
extern "C" void kernel_launch(void* const* d_in, const int* in_sizes, int n_in,
                              void* d_out, int out_size) {
    const float* traj      = (const float*)d_in[0];
    const float* gcn_w     = (const float*)d_in[1];
    const float* gcn_b     = (const float*)d_in[2];
    const float* in_proj_w = (const float*)d_in[3];
    const float* in_proj_b = (const float*)d_in[4];
    const float* out_proj_w= (const float*)d_in[5];
    const float* out_proj_b= (const float*)d_in[6];
    // d_in[7]=va_w, d_in[8]=va_b : unused (uniform softmaxes)
    const float* w_ih      = (const float*)d_in[9];
    const float* w_hh      = (const float*)d_in[10];
    const float* b_ih      = (const float*)d_in[11];
    const float* b_hh      = (const float*)d_in[12];
    const float* lin1_w    = (const float*)d_in[13];
    const float* lin1_b    = (const float*)d_in[14];
    const float* lin2_w    = (const float*)d_in[15];
    const float* lin2_b    = (const float*)d_in[16];
    float* out = (float*)d_out;

    float *pG, *pPk, *pF1, *pWbig, *pbatt, *pbihh, *pXT, *pLT, *pH1;
    cudaGetSymbolAddress((void**)&pG,    d_G);
    cudaGetSymbolAddress((void**)&pPk,   d_Pk);
    cudaGetSymbolAddress((void**)&pF1,   d_F1);
    cudaGetSymbolAddress((void**)&pWbig, d_Wbig);
    cudaGetSymbolAddress((void**)&pbatt, d_batt);
    cudaGetSymbolAddress((void**)&pbihh, d_bihh);
    cudaGetSymbolAddress((void**)&pXT,   d_XT);
    cudaGetSymbolAddress((void**)&pLT,   d_LT);
    cudaGetSymbolAddress((void**)&pH1,   d_H1);

    static int smem_set = 0;
    if (!smem_set) {
        cudaFuncSetAttribute(k_lstm, cudaFuncAttributeMaxDynamicSharedMemorySize,
                             SM_TOTAL);
        smem_set = 1;
    }

    const float* bv = in_proj_b + 2 * D_;
    const float* Wv = in_proj_w + (size_t)2 * D_ * D_;
    const int KQ = D_ / 4;                // 64 per split-K=4 part

    k_init<<<ROWS, 256>>>(traj, gcn_w, gcn_b);

    k_gemv<<<32, 256>>>(out_proj_w, D_, bv, out_proj_b, nullptr, pbatt, D_);
    k_gemv<<<256, 256>>>(w_ih, D_, pbatt, b_ih, b_hh, pbihh, G4);

    // F1 = w_ih @ Wop  (NN split-K=4)
    sgemm64b<<<dim3(D_ / 128, G4 / 64, 4), 256>>>(
        w_ih, out_proj_w, nullptr, pPk, G4, D_, KQ, 4 | 8 | 32,
        D_, D_, (size_t)KQ, (size_t)KQ * D_);
    k_addn<<<(G4 * D_ / 4 + 255) / 256, 256>>>(pPk, pF1, G4 * D_ / 4, 4);

    // Wbig = F1 @ Wv   (NN split-K=4)
    sgemm64b<<<dim3(D_ / 128, G4 / 64, 4), 256>>>(
        pF1, Wv, nullptr, pPk, G4, D_, KQ, 4 | 8 | 32,
        D_, D_, (size_t)KQ, (size_t)KQ * D_);
    k_addn<<<(G4 * D_ / 4 + 255) / 256, 256>>>(pPk, pWbig, G4 * D_ / 4, 4);

    // XT = Wbig @ G^T + bias_x[m]   --- TF32 tensor cores ---
    sgemm_nt_tf32<<<dim3(ROWS / 128, G4 / 128), 256>>>(
        pWbig, pG, pbihh, pXT, G4, ROWS, D_);

    // persistent LSTM
    k_lstm<<<NBLK, 256, SM_TOTAL>>>(w_hh);

    // H1 = relu(L @ lin1_w^T + b)  TN (non-split, R11 proven)
    sgemm64b<<<dim3(D_ / 128, ROWS / 64), 256>>>(
        pLT, lin1_w, lin1_b, pH1, ROWS, D_, LH, 1 | 16,
        ROWS, LH, 0, 0);

    // out = H1 @ lin2_w^T + b, permuted store
    sgemm64b<<<dim3(128 / 128, ROWS / 64), 256>>>(
        pH1, lin2_w, lin2_b, out, ROWS, 128, D_, 2,
        D_, D_, 0, 0);
}

// round 14
// speedup vs baseline: 1.2424x; 1.1691x over previous
#include <cuda_runtime.h>
#include <math.h>

// ----- problem dims -----
#define B_    32
#define T_    100
#define NN_   32
#define F_    8
#define D_    256
#define LH    512
#define G4    2048      // 4*LH
#define ROWS  3200      // B_*T_  (row = t*32 + b)
#define NBLK  128       // persistent LSTM grid

typedef unsigned long long ull;
typedef unsigned int uint;

// ----- device scratch -----
__device__ float d_G   [ROWS * D_];
__device__ float d_F1  [G4 * D_];     // w_ih @ Wop
__device__ float d_Wbig[G4 * D_];     // w_ih @ Wop @ Wv
__device__ float d_batt[D_];          // Wop@bv + bop
__device__ float d_bihh[G4];          // w_ih@batt + b_ih + b_hh
__device__ float d_XT  [G4 * ROWS];   // X^T: [gate*512+j][t*32+b]
__device__ float d_hbuf[2][B_ * LH];  // float4-grouped k-major
__device__ float d_LT  [LH * ROWS];   // L^T: [j][t*32+b]
__device__ float d_H1  [ROWS * D_];
__device__ int   d_bar;               // central barrier counter

__device__ __forceinline__ void ffma2(ull& d, ull a, ull b) {
    asm("fma.rn.f32x2 %0, %1, %2, %0;" : "+l"(d) : "l"(a), "l"(b));
}
__device__ __forceinline__ uint f2tf32(float x) {
    uint r;
    asm("cvt.rna.tf32.f32 %0, %1;" : "=r"(r) : "f"(x));
    return r;
}
__device__ __forceinline__ float tanh_fast(float x) {
    float ax = fabsf(x);
    float e  = __expf(-2.0f * ax);
    float t  = __fdividef(1.0f - e, 1.0f + e);
    return copysignf(t, x);
}
__device__ __forceinline__ float sigm(float x) {
    return 1.0f / (1.0f + __expf(-x));
}
__device__ __forceinline__ void red_release_add(int* p, int v) {
    asm volatile("red.release.gpu.global.add.s32 [%0], %1;" :: "l"(p), "r"(v) : "memory");
}
__device__ __forceinline__ int ld_acq(const int* p) {
    int v;
    asm volatile("ld.acquire.gpu.global.b32 %0, [%1];" : "=r"(v) : "l"(p) : "memory");
    return v;
}

// ======================================================================
// k_init: G = relu(mean_n(traj) @ gcn_w + gcn_b); also zero h[0], bar
// ======================================================================
__global__ void k_init(const float* __restrict__ traj,
                       const float* __restrict__ gw,
                       const float* __restrict__ gb) {
    int row = blockIdx.x;
    int t = row >> 5, b = row & 31;
    __shared__ float s[NN_ * F_];
    __shared__ float m[F_];
    int tid = threadIdx.x;

    if (row < 64) d_hbuf[0][row * 256 + tid] = 0.0f;
    if (row == 0 && tid == 0) d_bar = 0;

    const float* p = traj + (size_t)((b * T_ + t) * NN_) * F_;
    s[tid] = p[tid];
    __syncthreads();
    if (tid < F_) {
        float acc = 0.0f;
        #pragma unroll
        for (int n = 0; n < NN_; n++) acc += s[n * F_ + tid];
        m[tid] = acc * (1.0f / 32.0f);
    }
    __syncthreads();
    float acc = gb[tid];
    #pragma unroll
    for (int f = 0; f < F_; f++) acc += m[f] * gw[f * D_ + tid];
    d_G[(size_t)row * D_ + tid] = fmaxf(acc, 0.0f);
}

// ======================================================================
// GEMV (warp-per-row)
// ======================================================================
__global__ void k_gemv(const float* __restrict__ W, int K,
                       const float* __restrict__ x,
                       const float* __restrict__ add1,
                       const float* __restrict__ add2,
                       float* __restrict__ out, int M) {
    int gw   = (blockIdx.x * blockDim.x + threadIdx.x) >> 5;
    int lane = threadIdx.x & 31;
    if (gw >= M) return;
    float s = 0.0f;
    for (int k = lane; k < K; k += 32)
        s += W[(size_t)gw * K + k] * x[k];
    #pragma unroll
    for (int off = 16; off > 0; off >>= 1)
        s += __shfl_xor_sync(0xffffffff, s, off);
    if (lane == 0) {
        float r = s + add1[gw];
        if (add2) r += add2[gw];
        out[gw] = r;
    }
}

// ======================================================================
// TF32 GEMM template.  C[M,N] = A[M,K] @ B[N,K]^T (logical) + bias
// AKM=0: A stored row-major [M][K] ld lda  -> tile [row][k] pad 36
// AKM=1: A stored k-major  [K][M] ld lda  -> tile [k][row] stride 136
// BKM likewise for B (logical [N][K]; BKM=1 means stored [K][N] ld ldb)
// BMODE: 0 none, 1 bias[m], 2 bias[n].  RELU, PERM (row -> b*T+t) flags.
// BM=BN=128, BK=32, 256 threads = 8 warps (2m x 4n), mma.m16n8k8.tf32.
// Bank math: pad36 frag reads -> bank (4*row+k)%32 distinct; stride136
// frag reads -> bank (8k+row)%32 distinct; all stagings are LDG.128 ->
// aligned STS.128, conflict-free.
// ======================================================================
template<int AKM, int BKM, int BMODE, int RELU, int PERM>
__global__ void __launch_bounds__(256)
tf32gemm(const float* __restrict__ A, const float* __restrict__ Bm,
         const float* __restrict__ bias, float* __restrict__ C,
         int M, int N, int K, int lda, int ldb) {
    constexpr int ASZ = AKM ? 32 * 136 : 128 * 36;
    constexpr int BSZ = BKM ? 32 * 136 : 128 * 36;
    __shared__ __align__(16) uint As[ASZ];
    __shared__ __align__(16) uint Bs[BSZ];

    int tid = threadIdx.x, lane = tid & 31, wid = tid >> 5;
    int g = lane >> 2, t = lane & 3;
    int warp_m = wid >> 2, warp_n = wid & 3;
    int m0 = blockIdx.y * 128, n0 = blockIdx.x * 128;

    float c[4][4][4];
    #pragma unroll
    for (int i = 0; i < 4; i++)
        #pragma unroll
        for (int j = 0; j < 4; j++)
            #pragma unroll
            for (int e = 0; e < 4; e++) c[i][j][e] = 0.0f;

    for (int k0 = 0; k0 < K; k0 += 32) {
        // ---- stage A ----
        #pragma unroll
        for (int i = 0; i < 4; i++) {
            int idx = tid + i * 256;
            if constexpr (AKM == 0) {
                int r  = idx >> 3;
                int kq = (idx & 7) * 4;
                float4 va = *(const float4*)&A[(size_t)(m0 + r) * lda + k0 + kq];
                uint4 w = make_uint4(f2tf32(va.x), f2tf32(va.y),
                                     f2tf32(va.z), f2tf32(va.w));
                *(uint4*)&As[r * 36 + kq] = w;
            } else {
                int kk = idx >> 5;
                int cc = (idx & 31) * 4;
                float4 va = *(const float4*)&A[(size_t)(k0 + kk) * lda + m0 + cc];
                uint4 w = make_uint4(f2tf32(va.x), f2tf32(va.y),
                                     f2tf32(va.z), f2tf32(va.w));
                *(uint4*)&As[kk * 136 + cc] = w;
            }
        }
        // ---- stage B ----
        #pragma unroll
        for (int i = 0; i < 4; i++) {
            int idx = tid + i * 256;
            if constexpr (BKM == 0) {
                int r  = idx >> 3;
                int kq = (idx & 7) * 4;
                float4 vb = *(const float4*)&Bm[(size_t)(n0 + r) * ldb + k0 + kq];
                uint4 w = make_uint4(f2tf32(vb.x), f2tf32(vb.y),
                                     f2tf32(vb.z), f2tf32(vb.w));
                *(uint4*)&Bs[r * 36 + kq] = w;
            } else {
                int kk = idx >> 5;
                int cc = (idx & 31) * 4;
                float4 vb = *(const float4*)&Bm[(size_t)(k0 + kk) * ldb + n0 + cc];
                uint4 w = make_uint4(f2tf32(vb.x), f2tf32(vb.y),
                                     f2tf32(vb.z), f2tf32(vb.w));
                *(uint4*)&Bs[kk * 136 + cc] = w;
            }
        }
        __syncthreads();

        #pragma unroll
        for (int kb = 0; kb < 32; kb += 8) {
            uint bfr[4][2];
            #pragma unroll
            for (int nf = 0; nf < 4; nf++) {
                int n = warp_n * 32 + nf * 8 + g;
                if constexpr (BKM == 0) {
                    bfr[nf][0] = Bs[n * 36 + kb + t];
                    bfr[nf][1] = Bs[n * 36 + kb + t + 4];
                } else {
                    bfr[nf][0] = Bs[(kb + t) * 136 + n];
                    bfr[nf][1] = Bs[(kb + t + 4) * 136 + n];
                }
            }
            #pragma unroll
            for (int mf = 0; mf < 4; mf++) {
                int m = warp_m * 64 + mf * 16 + g;
                uint a0, a1, a2, a3;
                if constexpr (AKM == 0) {
                    a0 = As[m * 36 + kb + t];       a1 = As[(m + 8) * 36 + kb + t];
                    a2 = As[m * 36 + kb + t + 4];   a3 = As[(m + 8) * 36 + kb + t + 4];
                } else {
                    a0 = As[(kb + t) * 136 + m];     a1 = As[(kb + t) * 136 + m + 8];
                    a2 = As[(kb + t + 4) * 136 + m]; a3 = As[(kb + t + 4) * 136 + m + 8];
                }
                #pragma unroll
                for (int nf = 0; nf < 4; nf++) {
                    asm volatile(
                        "mma.sync.aligned.m16n8k8.row.col.f32.tf32.tf32.f32 "
                        "{%0,%1,%2,%3}, {%4,%5,%6,%7}, {%8,%9}, {%0,%1,%2,%3};"
                        : "+f"(c[mf][nf][0]), "+f"(c[mf][nf][1]),
                          "+f"(c[mf][nf][2]), "+f"(c[mf][nf][3])
                        : "r"(a0), "r"(a1), "r"(a2), "r"(a3),
                          "r"(bfr[nf][0]), "r"(bfr[nf][1]));
                }
            }
        }
        __syncthreads();
    }

    // ---- epilogue ----
    #pragma unroll
    for (int mf = 0; mf < 4; mf++) {
        int mg = m0 + warp_m * 64 + mf * 16 + g;
        float b0v = 0.0f, b1v = 0.0f;
        if constexpr (BMODE == 1) { b0v = bias[mg]; b1v = bias[mg + 8]; }
        size_t row0, row1;
        if constexpr (PERM) {
            row0 = (size_t)((mg & 31) * T_ + (mg >> 5));
            row1 = (size_t)(((mg + 8) & 31) * T_ + ((mg + 8) >> 5));
        } else {
            row0 = (size_t)mg; row1 = (size_t)(mg + 8);
        }
        #pragma unroll
        for (int nf = 0; nf < 4; nf++) {
            int ng = n0 + warp_n * 32 + nf * 8 + t * 2;
            float bnx = 0.0f, bny = 0.0f;
            if constexpr (BMODE == 2) {
                float2 bb = *(const float2*)&bias[ng];
                bnx = bb.x; bny = bb.y;
            }
            float2 v0 = make_float2(c[mf][nf][0] + b0v + bnx, c[mf][nf][1] + b0v + bny);
            float2 v1 = make_float2(c[mf][nf][2] + b1v + bnx, c[mf][nf][3] + b1v + bny);
            if constexpr (RELU) {
                v0.x = fmaxf(v0.x, 0.0f); v0.y = fmaxf(v0.y, 0.0f);
                v1.x = fmaxf(v1.x, 0.0f); v1.y = fmaxf(v1.y, 0.0f);
            }
            *(float2*)&C[row0 * N + ng] = v0;
            *(float2*)&C[row1 * N + ng] = v1;
        }
    }
}

// ======================================================================
// Persistent LSTM: 128 blocks x 256 threads; depth-4 h-load pipeline.
// ======================================================================
#define SM_WS4   0
#define SM_PACC  (SM_WS4 + 16 * 128 * 16)
#define SM_CS    (SM_PACC + 8 * 16 * 32 * 4)
#define SM_TOTAL (SM_CS + 128 * 4)

__global__ void __launch_bounds__(256, 1)
k_lstm(const float* __restrict__ whh) {
    extern __shared__ char smem[];
    float4* ws4  = (float4*)(smem + SM_WS4);
    float*  pacc = (float*) (smem + SM_PACC);
    float*  cs   = (float*) (smem + SM_CS);

    int tid = threadIdx.x, lane = tid & 31, wrp = tid >> 5;
    int j0 = blockIdx.x * 4;

    #pragma unroll
    for (int i = 0; i < 8; i++) {
        int idx = i * 256 + tid;
        int r = idx >> 7, q = idx & 127;
        int rr = (r >> 2) * LH + j0 + (r & 3);
        ws4[r * 128 + q] = ((const float4*)whh)[(size_t)rr * 128 + q];
    }
    if (tid < 128) cs[tid] = 0.0f;
    __syncthreads();

    const int qbase = wrp * 16;
    const int pjj = tid >> 5;
    const int pb  = tid & 31;
    const size_t xbase = (size_t)(j0 + pjj) * ROWS + pb;
    const size_t gstr  = (size_t)LH * ROWS;

    float xg0 = 0, xg1 = 0, xg2 = 0, xg3 = 0;
    if (tid < 128) {
        xg0 = __ldcg(&d_XT[xbase + 0 * gstr]);
        xg1 = __ldcg(&d_XT[xbase + 1 * gstr]);
        xg2 = __ldcg(&d_XT[xbase + 2 * gstr]);
        xg3 = __ldcg(&d_XT[xbase + 3 * gstr]);
    }

    for (int t = 0; t < T_; t++) {
        const float4* hin = (const float4*)d_hbuf[t & 1];

        float xn0 = 0, xn1 = 0, xn2 = 0, xn3 = 0;
        if (tid < 128 && t + 1 < T_) {
            size_t o = xbase + (t + 1) * 32;
            xn0 = __ldcg(&d_XT[o + 0 * gstr]);
            xn1 = __ldcg(&d_XT[o + 1 * gstr]);
            xn2 = __ldcg(&d_XT[o + 2 * gstr]);
            xn3 = __ldcg(&d_XT[o + 3 * gstr]);
        }

        float4 hq[4];
        #pragma unroll
        for (int i = 0; i < 4; i++)
            hq[i] = __ldcg(&hin[(qbase + i) * 32 + lane]);

        ull alo[16], ahi[16];
        #pragma unroll
        for (int r = 0; r < 16; r++) { alo[r] = 0ULL; ahi[r] = 0ULL; }

        #pragma unroll
        for (int qq = 0; qq < 16; qq++) {
            float4 hv = hq[qq & 3];
            if (qq < 12)
                hq[qq & 3] = __ldcg(&hin[(qbase + qq + 4) * 32 + lane]);
            ull hlo = ((ull*)&hv)[0], hhi = ((ull*)&hv)[1];
            #pragma unroll
            for (int r = 0; r < 16; r++) {
                float4 wv = ws4[r * 128 + qbase + qq];
                ffma2(alo[r], ((ull*)&wv)[0], hlo);
                ffma2(ahi[r], ((ull*)&wv)[1], hhi);
            }
        }
        #pragma unroll
        for (int r = 0; r < 16; r++) {
            float2 a = *(float2*)&alo[r], b = *(float2*)&ahi[r];
            pacc[(wrp * 16 + r) * 32 + lane] = a.x + a.y + b.x + b.y;
        }
        __syncthreads();

        if (tid < 128) {
            float zi = xg0, zf = xg1, zg = xg2, zo = xg3;
            #pragma unroll
            for (int w = 0; w < 8; w++) {
                const float* pw = pacc + (w * 16) * 32 + pb;
                zi += pw[( 0 + pjj) * 32];
                zf += pw[( 4 + pjj) * 32];
                zg += pw[( 8 + pjj) * 32];
                zo += pw[(12 + pjj) * 32];
            }
            float cp = cs[pjj * 32 + pb];
            float ig = sigm(zi), fg = sigm(zf);
            float gg = tanh_fast(zg), og = sigm(zo);
            float cn = fg * cp + ig * gg;
            float hn = og * tanh_fast(cn);
            cs[pjj * 32 + pb] = cn;
            d_hbuf[(t + 1) & 1][blockIdx.x * 128 + pb * 4 + pjj] = hn;
            d_LT[(size_t)(j0 + pjj) * ROWS + t * 32 + pb] = hn;
        }
        xg0 = xn0; xg1 = xn1; xg2 = xn2; xg3 = xn3;

        __syncthreads();
        if (tid == 0) {
            red_release_add(&d_bar, 1);
            while (ld_acq(&d_bar) < NBLK * (t + 1)) { }
        }
        __syncthreads();
    }
}

// ======================================================================
extern "C" void kernel_launch(void* const* d_in, const int* in_sizes, int n_in,
                              void* d_out, int out_size) {
    const float* traj      = (const float*)d_in[0];
    const float* gcn_w     = (const float*)d_in[1];
    const float* gcn_b     = (const float*)d_in[2];
    const float* in_proj_w = (const float*)d_in[3];
    const float* in_proj_b = (const float*)d_in[4];
    const float* out_proj_w= (const float*)d_in[5];
    const float* out_proj_b= (const float*)d_in[6];
    // d_in[7]=va_w, d_in[8]=va_b : unused (uniform softmaxes)
    const float* w_ih      = (const float*)d_in[9];
    const float* w_hh      = (const float*)d_in[10];
    const float* b_ih      = (const float*)d_in[11];
    const float* b_hh      = (const float*)d_in[12];
    const float* lin1_w    = (const float*)d_in[13];
    const float* lin1_b    = (const float*)d_in[14];
    const float* lin2_w    = (const float*)d_in[15];
    const float* lin2_b    = (const float*)d_in[16];
    float* out = (float*)d_out;

    float *pG, *pF1, *pWbig, *pbatt, *pbihh, *pXT, *pLT, *pH1;
    cudaGetSymbolAddress((void**)&pG,    d_G);
    cudaGetSymbolAddress((void**)&pF1,   d_F1);
    cudaGetSymbolAddress((void**)&pWbig, d_Wbig);
    cudaGetSymbolAddress((void**)&pbatt, d_batt);
    cudaGetSymbolAddress((void**)&pbihh, d_bihh);
    cudaGetSymbolAddress((void**)&pXT,   d_XT);
    cudaGetSymbolAddress((void**)&pLT,   d_LT);
    cudaGetSymbolAddress((void**)&pH1,   d_H1);

    static int smem_set = 0;
    if (!smem_set) {
        cudaFuncSetAttribute(k_lstm, cudaFuncAttributeMaxDynamicSharedMemorySize,
                             SM_TOTAL);
        smem_set = 1;
    }

    const float* bv = in_proj_b + 2 * D_;
    const float* Wv = in_proj_w + (size_t)2 * D_ * D_;

    k_init<<<ROWS, 256>>>(traj, gcn_w, gcn_b);

    k_gemv<<<32, 256>>>(out_proj_w, D_, bv, out_proj_b, nullptr, pbatt, D_);
    k_gemv<<<256, 256>>>(w_ih, D_, pbatt, b_ih, b_hh, pbihh, G4);

    // F1 = w_ih @ Wop    (A row-major, B k-major [K][N])
    tf32gemm<0, 1, 0, 0, 0><<<dim3(D_ / 128, G4 / 128), 256>>>(
        w_ih, out_proj_w, nullptr, pF1, G4, D_, D_, D_, D_);

    // Wbig = F1 @ Wv     (A row-major, B k-major)
    tf32gemm<0, 1, 0, 0, 0><<<dim3(D_ / 128, G4 / 128), 256>>>(
        pF1, Wv, nullptr, pWbig, G4, D_, D_, D_, D_);

    // XT = Wbig @ G^T + bias_x[m]   (both row-major NT, bias per-m)
    tf32gemm<0, 0, 1, 0, 0><<<dim3(ROWS / 128, G4 / 128), 256>>>(
        pWbig, pG, pbihh, pXT, G4, ROWS, D_, D_, D_);

    // persistent LSTM
    k_lstm<<<NBLK, 256, SM_TOTAL>>>(w_hh);

    // H1 = relu(L @ lin1_w^T + b)   (A = LT k-major [K][M] lda=ROWS,
    //                                B = lin1_w row-major, bias per-n, relu)
    tf32gemm<1, 0, 2, 1, 0><<<dim3(D_ / 128, ROWS / 128), 256>>>(
        pLT, lin1_w, lin1_b, pH1, ROWS, D_, LH, ROWS, LH);

    // out = H1 @ lin2_w^T + b       (row-major NT, bias per-n, permuted rows)
    tf32gemm<0, 0, 2, 0, 1><<<dim3(128 / 128, ROWS / 128), 256>>>(
        pH1, lin2_w, lin2_b, out, ROWS, 128, D_, D_, D_);
}

// round 15
// speedup vs baseline: 1.6115x; 1.2971x over previous
#include <cuda_runtime.h>
#include <math.h>

// ----- problem dims -----
#define B_    32
#define T_    100
#define NN_   32
#define F_    8
#define D_    256
#define LH    512
#define G4    2048      // 4*LH
#define ROWS  3200      // B_*T_  (row = t*32 + b)
#define NBLK  128       // persistent LSTM grid
#define PAD   34        // pacc row stride (floats)

typedef unsigned long long ull;
typedef unsigned int uint;

// ----- device scratch -----
__device__ float d_G   [ROWS * D_];
__device__ float d_Pk  [4 * G4 * D_]; // split-K partials (folds)
__device__ float d_F1  [G4 * D_];     // w_ih @ Wop
__device__ float d_Wbig[G4 * D_];     // w_ih @ Wop @ Wv
__device__ float d_batt[D_];          // Wop@bv + bop
__device__ float d_bihh[G4];          // w_ih@batt + b_ih + b_hh
__device__ float d_XT  [G4 * ROWS];   // X^T: [gate*512+j][t*32+b]
__device__ float d_hbuf[2][B_ * LH];  // q-grouped: (j>>2)*128 + b*4 + (j&3)
__device__ float d_LT  [LH * ROWS];   // L^T: [j][t*32+b]
__device__ float d_H1  [ROWS * D_];
__device__ int   d_bar;               // central barrier counter

__device__ __forceinline__ uint f2tf32(float x) {
    uint r;
    asm("cvt.rna.tf32.f32 %0, %1;" : "=r"(r) : "f"(x));
    return r;
}
__device__ __forceinline__ float tanh_fast(float x) {
    float ax = fabsf(x);
    float e  = __expf(-2.0f * ax);
    float t  = __fdividef(1.0f - e, 1.0f + e);
    return copysignf(t, x);
}
__device__ __forceinline__ float sigm(float x) {
    return 1.0f / (1.0f + __expf(-x));
}
__device__ __forceinline__ void red_release_add(int* p, int v) {
    asm volatile("red.release.gpu.global.add.s32 [%0], %1;" :: "l"(p), "r"(v) : "memory");
}
__device__ __forceinline__ int ld_acq(const int* p) {
    int v;
    asm volatile("ld.acquire.gpu.global.b32 %0, [%1];" : "=r"(v) : "l"(p) : "memory");
    return v;
}

// ======================================================================
// k_init: G = relu(mean_n(traj) @ gcn_w + gcn_b); also zero h[0], bar
// ======================================================================
__global__ void k_init(const float* __restrict__ traj,
                       const float* __restrict__ gw,
                       const float* __restrict__ gb) {
    int row = blockIdx.x;
    int t = row >> 5, b = row & 31;
    __shared__ float s[NN_ * F_];
    __shared__ float m[F_];
    int tid = threadIdx.x;

    if (row < 64) d_hbuf[0][row * 256 + tid] = 0.0f;
    if (row == 0 && tid == 0) d_bar = 0;

    const float* p = traj + (size_t)((b * T_ + t) * NN_) * F_;
    s[tid] = p[tid];
    __syncthreads();
    if (tid < F_) {
        float acc = 0.0f;
        #pragma unroll
        for (int n = 0; n < NN_; n++) acc += s[n * F_ + tid];
        m[tid] = acc * (1.0f / 32.0f);
    }
    __syncthreads();
    float acc = gb[tid];
    #pragma unroll
    for (int f = 0; f < F_; f++) acc += m[f] * gw[f * D_ + tid];
    d_G[(size_t)row * D_ + tid] = fmaxf(acc, 0.0f);
}

// ======================================================================
// GEMV (warp-per-row)
// ======================================================================
__global__ void k_gemv(const float* __restrict__ W, int K,
                       const float* __restrict__ x,
                       const float* __restrict__ add1,
                       const float* __restrict__ add2,
                       float* __restrict__ out, int M) {
    int gw   = (blockIdx.x * blockDim.x + threadIdx.x) >> 5;
    int lane = threadIdx.x & 31;
    if (gw >= M) return;
    float s = 0.0f;
    for (int k = lane; k < K; k += 32)
        s += W[(size_t)gw * K + k] * x[k];
    #pragma unroll
    for (int off = 16; off > 0; off >>= 1)
        s += __shfl_xor_sync(0xffffffff, s, off);
    if (lane == 0) {
        float r = s + add1[gw];
        if (add2) r += add2[gw];
        out[gw] = r;
    }
}

// ======================================================================
// k_addn: C[i] = sum_{p<nparts} P[p*len4 + i]   (float4 elements)
// ======================================================================
__global__ void k_addn(const float* __restrict__ P, float* __restrict__ C,
                       int len4, int nparts) {
    int i = blockIdx.x * blockDim.x + threadIdx.x;
    if (i < len4) {
        float4 v = ((const float4*)P)[i];
        for (int p = 1; p < nparts; p++) {
            float4 a = ((const float4*)P)[(size_t)p * len4 + i];
            v.x += a.x; v.y += a.y; v.z += a.z; v.w += a.w;
        }
        ((float4*)C)[i] = v;
    }
}

// ======================================================================
// Scalar fp32 SGEMM BM=64 BN=128 BK=16 (proven R12): NN + split-K only
// used for the weight folds (exact fp32 — protects the error budget).
// ======================================================================
__global__ void __launch_bounds__(256)
sgemm_fold(const float* __restrict__ A, const float* __restrict__ Bm,
           float* __restrict__ C, int M, int N, int K,
           int lda, int ldb, size_t kadvA, size_t kadvB) {
    __shared__ __align__(16) float As[16][64];
    __shared__ __align__(16) float Bs[16][128];

    int tid = threadIdx.x;
    int m0 = blockIdx.y * 64, n0 = blockIdx.x * 128;
    int tm = (tid >> 4) * 4, tn = (tid & 15) * 8;

    A  += blockIdx.z * kadvA;
    Bm += blockIdx.z * kadvB;
    C  += (size_t)blockIdx.z * M * N;

    float acc[4][8];
    #pragma unroll
    for (int i = 0; i < 4; i++)
        #pragma unroll
        for (int j = 0; j < 8; j++) acc[i][j] = 0.0f;

    for (int k0 = 0; k0 < K; k0 += 16) {
        {   // A row-major
            int r  = tid >> 2;
            int kq = (tid & 3) * 4;
            float4 va = *(const float4*)&A[(size_t)(m0 + r) * lda + k0 + kq];
            As[kq + 0][r] = va.x; As[kq + 1][r] = va.y;
            As[kq + 2][r] = va.z; As[kq + 3][r] = va.w;
        }
        #pragma unroll
        for (int i = 0; i < 2; i++) {  // B k-major [K][N]
            int idx = tid + i * 256;
            int kk = idx >> 5;
            int c  = (idx & 31) * 4;
            float4 vb = *(const float4*)&Bm[(size_t)(k0 + kk) * ldb + n0 + c];
            *(float4*)&Bs[kk][c] = vb;
        }
        __syncthreads();
        #pragma unroll
        for (int kk = 0; kk < 16; kk++) {
            float a[4], b[8];
            *(float4*)&a[0] = *(const float4*)&As[kk][tm];
            *(float4*)&b[0] = *(const float4*)&Bs[kk][tn];
            *(float4*)&b[4] = *(const float4*)&Bs[kk][tn + 4];
            #pragma unroll
            for (int i = 0; i < 4; i++)
                #pragma unroll
                for (int j = 0; j < 8; j++)
                    acc[i][j] += a[i] * b[j];
        }
        __syncthreads();
    }

    #pragma unroll
    for (int i = 0; i < 4; i++) {
        float* crow = C + (size_t)(m0 + tm + i) * N;
        #pragma unroll
        for (int j = 0; j < 8; j += 4) {
            float4 v = make_float4(acc[i][j], acc[i][j+1], acc[i][j+2], acc[i][j+3]);
            *(float4*)&crow[n0 + tn + j] = v;
        }
    }
}

// ======================================================================
// TF32 GEMM template (proven R14).  C = A[M,K] @ B[N,K]^T + bias
// AKM/BKM: 0 row-major (pad-36 tile), 1 k-major (stride-136 tile).
// BMODE: 0 none, 1 bias[m], 2 bias[n].  RELU, PERM flags.
// ======================================================================
template<int AKM, int BKM, int BMODE, int RELU, int PERM>
__global__ void __launch_bounds__(256)
tf32gemm(const float* __restrict__ A, const float* __restrict__ Bm,
         const float* __restrict__ bias, float* __restrict__ C,
         int M, int N, int K, int lda, int ldb) {
    constexpr int ASZ = AKM ? 32 * 136 : 128 * 36;
    constexpr int BSZ = BKM ? 32 * 136 : 128 * 36;
    __shared__ __align__(16) uint As[ASZ];
    __shared__ __align__(16) uint Bs[BSZ];

    int tid = threadIdx.x, lane = tid & 31, wid = tid >> 5;
    int g = lane >> 2, t = lane & 3;
    int warp_m = wid >> 2, warp_n = wid & 3;
    int m0 = blockIdx.y * 128, n0 = blockIdx.x * 128;

    float c[4][4][4];
    #pragma unroll
    for (int i = 0; i < 4; i++)
        #pragma unroll
        for (int j = 0; j < 4; j++)
            #pragma unroll
            for (int e = 0; e < 4; e++) c[i][j][e] = 0.0f;

    for (int k0 = 0; k0 < K; k0 += 32) {
        #pragma unroll
        for (int i = 0; i < 4; i++) {
            int idx = tid + i * 256;
            if constexpr (AKM == 0) {
                int r  = idx >> 3;
                int kq = (idx & 7) * 4;
                float4 va = *(const float4*)&A[(size_t)(m0 + r) * lda + k0 + kq];
                uint4 w = make_uint4(f2tf32(va.x), f2tf32(va.y),
                                     f2tf32(va.z), f2tf32(va.w));
                *(uint4*)&As[r * 36 + kq] = w;
            } else {
                int kk = idx >> 5;
                int cc = (idx & 31) * 4;
                float4 va = *(const float4*)&A[(size_t)(k0 + kk) * lda + m0 + cc];
                uint4 w = make_uint4(f2tf32(va.x), f2tf32(va.y),
                                     f2tf32(va.z), f2tf32(va.w));
                *(uint4*)&As[kk * 136 + cc] = w;
            }
        }
        #pragma unroll
        for (int i = 0; i < 4; i++) {
            int idx = tid + i * 256;
            if constexpr (BKM == 0) {
                int r  = idx >> 3;
                int kq = (idx & 7) * 4;
                float4 vb = *(const float4*)&Bm[(size_t)(n0 + r) * ldb + k0 + kq];
                uint4 w = make_uint4(f2tf32(vb.x), f2tf32(vb.y),
                                     f2tf32(vb.z), f2tf32(vb.w));
                *(uint4*)&Bs[r * 36 + kq] = w;
            } else {
                int kk = idx >> 5;
                int cc = (idx & 31) * 4;
                float4 vb = *(const float4*)&Bm[(size_t)(k0 + kk) * ldb + n0 + cc];
                uint4 w = make_uint4(f2tf32(vb.x), f2tf32(vb.y),
                                     f2tf32(vb.z), f2tf32(vb.w));
                *(uint4*)&Bs[kk * 136 + cc] = w;
            }
        }
        __syncthreads();

        #pragma unroll
        for (int kb = 0; kb < 32; kb += 8) {
            uint bfr[4][2];
            #pragma unroll
            for (int nf = 0; nf < 4; nf++) {
                int n = warp_n * 32 + nf * 8 + g;
                if constexpr (BKM == 0) {
                    bfr[nf][0] = Bs[n * 36 + kb + t];
                    bfr[nf][1] = Bs[n * 36 + kb + t + 4];
                } else {
                    bfr[nf][0] = Bs[(kb + t) * 136 + n];
                    bfr[nf][1] = Bs[(kb + t + 4) * 136 + n];
                }
            }
            #pragma unroll
            for (int mf = 0; mf < 4; mf++) {
                int m = warp_m * 64 + mf * 16 + g;
                uint a0, a1, a2, a3;
                if constexpr (AKM == 0) {
                    a0 = As[m * 36 + kb + t];       a1 = As[(m + 8) * 36 + kb + t];
                    a2 = As[m * 36 + kb + t + 4];   a3 = As[(m + 8) * 36 + kb + t + 4];
                } else {
                    a0 = As[(kb + t) * 136 + m];     a1 = As[(kb + t) * 136 + m + 8];
                    a2 = As[(kb + t + 4) * 136 + m]; a3 = As[(kb + t + 4) * 136 + m + 8];
                }
                #pragma unroll
                for (int nf = 0; nf < 4; nf++) {
                    asm volatile(
                        "mma.sync.aligned.m16n8k8.row.col.f32.tf32.tf32.f32 "
                        "{%0,%1,%2,%3}, {%4,%5,%6,%7}, {%8,%9}, {%0,%1,%2,%3};"
                        : "+f"(c[mf][nf][0]), "+f"(c[mf][nf][1]),
                          "+f"(c[mf][nf][2]), "+f"(c[mf][nf][3])
                        : "r"(a0), "r"(a1), "r"(a2), "r"(a3),
                          "r"(bfr[nf][0]), "r"(bfr[nf][1]));
                }
            }
        }
        __syncthreads();
    }

    #pragma unroll
    for (int mf = 0; mf < 4; mf++) {
        int mg = m0 + warp_m * 64 + mf * 16 + g;
        float b0v = 0.0f, b1v = 0.0f;
        if constexpr (BMODE == 1) { b0v = bias[mg]; b1v = bias[mg + 8]; }
        size_t row0, row1;
        if constexpr (PERM) {
            row0 = (size_t)((mg & 31) * T_ + (mg >> 5));
            row1 = (size_t)(((mg + 8) & 31) * T_ + ((mg + 8) >> 5));
        } else {
            row0 = (size_t)mg; row1 = (size_t)(mg + 8);
        }
        #pragma unroll
        for (int nf = 0; nf < 4; nf++) {
            int ng = n0 + warp_n * 32 + nf * 8 + t * 2;
            float bnx = 0.0f, bny = 0.0f;
            if constexpr (BMODE == 2) {
                float2 bb = *(const float2*)&bias[ng];
                bnx = bb.x; bny = bb.y;
            }
            float2 v0 = make_float2(c[mf][nf][0] + b0v + bnx, c[mf][nf][1] + b0v + bny);
            float2 v1 = make_float2(c[mf][nf][2] + b1v + bnx, c[mf][nf][3] + b1v + bny);
            if constexpr (RELU) {
                v0.x = fmaxf(v0.x, 0.0f); v0.y = fmaxf(v0.y, 0.0f);
                v1.x = fmaxf(v1.x, 0.0f); v1.y = fmaxf(v1.y, 0.0f);
            }
            *(float2*)&C[row0 * N + ng] = v0;
            *(float2*)&C[row1 * N + ng] = v1;
        }
    }
}

// ======================================================================
// Persistent LSTM, tensor-core edition. 128 blocks x 256 threads.
// Per block/step: Z[16 gate-rows][32 b] = Whh_slice @ h  via
// mma.m16n8k8.tf32. 8 warps split K (64 each). w_hh fragments live in
// registers (compensated: whi + wlo, both tf32 -> ~fp32 weight accuracy).
// h fragments read DIRECTLY from global q-grouped hbuf: per (kc,nf) the
// lane-varying offset is 4g+t = 0..31 -> perfectly coalesced LDG.32.
// Partials -> pacc (pad 34) -> 8-warp reduce + pointwise (unchanged).
// ======================================================================
__global__ void __launch_bounds__(256, 1)
k_lstm(const float* __restrict__ whh) {
    __shared__ float pacc[128 * PAD];
    __shared__ float cs[128];

    int tid = threadIdx.x, lane = tid & 31, wrp = tid >> 5;
    int g = lane >> 2, t = lane & 3;
    int j0 = blockIdx.x * 4;

    // ---- static A fragments: rows g and g+8 of the 16-row gate tile ----
    const int rr0 = ((g    ) >> 2) * LH + j0 + ((g    ) & 3);
    const int rr1 = ((g + 8) >> 2) * LH + j0 + ((g + 8) & 3);
    uint ahi[8][4], alo[8][4];
    #pragma unroll
    for (int kc = 0; kc < 8; kc++) {
        int kg = wrp * 64 + kc * 8 + t;
        float w00 = whh[(size_t)rr0 * LH + kg];
        float w10 = whh[(size_t)rr1 * LH + kg];
        float w01 = whh[(size_t)rr0 * LH + kg + 4];
        float w11 = whh[(size_t)rr1 * LH + kg + 4];
        ahi[kc][0] = f2tf32(w00); ahi[kc][1] = f2tf32(w10);
        ahi[kc][2] = f2tf32(w01); ahi[kc][3] = f2tf32(w11);
        alo[kc][0] = f2tf32(w00 - __uint_as_float(ahi[kc][0]));
        alo[kc][1] = f2tf32(w10 - __uint_as_float(ahi[kc][1]));
        alo[kc][2] = f2tf32(w01 - __uint_as_float(ahi[kc][2]));
        alo[kc][3] = f2tf32(w11 - __uint_as_float(ahi[kc][3]));
    }
    if (tid < 128) cs[tid] = 0.0f;
    __syncthreads();

    const int pjj = tid >> 5;          // pointwise mapping (tid<128)
    const int pb  = tid & 31;
    const size_t xbase = (size_t)(j0 + pjj) * ROWS + pb;
    const size_t gstr  = (size_t)LH * ROWS;

    float xg0 = 0, xg1 = 0, xg2 = 0, xg3 = 0;
    if (tid < 128) {
        xg0 = __ldcg(&d_XT[xbase + 0 * gstr]);
        xg1 = __ldcg(&d_XT[xbase + 1 * gstr]);
        xg2 = __ldcg(&d_XT[xbase + 2 * gstr]);
        xg3 = __ldcg(&d_XT[xbase + 3 * gstr]);
    }

    // per-(kc) base offsets into hbuf floats: (wrp*16 + 2kc)*128 + t
    const int hb0 = wrp * 16 * 128 + t;

    for (int tt = 0; tt < T_; tt++) {
        const float* hf = d_hbuf[tt & 1];

        float xn0 = 0, xn1 = 0, xn2 = 0, xn3 = 0;
        if (tid < 128 && tt + 1 < T_) {
            size_t o = xbase + (tt + 1) * 32;
            xn0 = __ldcg(&d_XT[o + 0 * gstr]);
            xn1 = __ldcg(&d_XT[o + 1 * gstr]);
            xn2 = __ldcg(&d_XT[o + 2 * gstr]);
            xn3 = __ldcg(&d_XT[o + 3 * gstr]);
        }

        float c[4][4];
        #pragma unroll
        for (int nf = 0; nf < 4; nf++)
            #pragma unroll
            for (int e = 0; e < 4; e++) c[nf][e] = 0.0f;

        #pragma unroll
        for (int kc = 0; kc < 8; kc++) {
            int base0 = hb0 + 2 * kc * 128;   // q = wrp*16 + 2kc
            int base1 = base0 + 128;          // q + 1
            uint bh[4][2];
            #pragma unroll
            for (int nf = 0; nf < 4; nf++) {
                int n4 = (nf * 8 + g) * 4;
                bh[nf][0] = f2tf32(__ldcg(&hf[base0 + n4]));
                bh[nf][1] = f2tf32(__ldcg(&hf[base1 + n4]));
            }
            #pragma unroll
            for (int nf = 0; nf < 4; nf++) {
                asm volatile(
                    "mma.sync.aligned.m16n8k8.row.col.f32.tf32.tf32.f32 "
                    "{%0,%1,%2,%3}, {%4,%5,%6,%7}, {%8,%9}, {%0,%1,%2,%3};"
                    : "+f"(c[nf][0]), "+f"(c[nf][1]), "+f"(c[nf][2]), "+f"(c[nf][3])
                    : "r"(ahi[kc][0]), "r"(ahi[kc][1]), "r"(ahi[kc][2]), "r"(ahi[kc][3]),
                      "r"(bh[nf][0]), "r"(bh[nf][1]));
                asm volatile(
                    "mma.sync.aligned.m16n8k8.row.col.f32.tf32.tf32.f32 "
                    "{%0,%1,%2,%3}, {%4,%5,%6,%7}, {%8,%9}, {%0,%1,%2,%3};"
                    : "+f"(c[nf][0]), "+f"(c[nf][1]), "+f"(c[nf][2]), "+f"(c[nf][3])
                    : "r"(alo[kc][0]), "r"(alo[kc][1]), "r"(alo[kc][2]), "r"(alo[kc][3]),
                      "r"(bh[nf][0]), "r"(bh[nf][1]));
            }
        }

        // D fragments -> pacc: rows g / g+8, cols 2t, 2t+1 (+ nf*8)
        #pragma unroll
        for (int nf = 0; nf < 4; nf++) {
            int col = nf * 8 + 2 * t;
            *(float2*)&pacc[(wrp * 16 + g    ) * PAD + col] = make_float2(c[nf][0], c[nf][1]);
            *(float2*)&pacc[(wrp * 16 + g + 8) * PAD + col] = make_float2(c[nf][2], c[nf][3]);
        }
        __syncthreads();

        // merged reduce + pointwise (tid < 128): warp=jj, lane=b
        if (tid < 128) {
            float zi = xg0, zf = xg1, zg = xg2, zo = xg3;
            #pragma unroll
            for (int w = 0; w < 8; w++) {
                const float* pw = pacc + (w * 16) * PAD + pb;
                zi += pw[( 0 + pjj) * PAD];
                zf += pw[( 4 + pjj) * PAD];
                zg += pw[( 8 + pjj) * PAD];
                zo += pw[(12 + pjj) * PAD];
            }
            float cp = cs[pjj * 32 + pb];
            float ig = sigm(zi), fg = sigm(zf);
            float gg = tanh_fast(zg), og = sigm(zo);
            float cn = fg * cp + ig * gg;
            float hn = og * tanh_fast(cn);
            cs[pjj * 32 + pb] = cn;
            d_hbuf[(tt + 1) & 1][blockIdx.x * 128 + pb * 4 + pjj] = hn;
            d_LT[(size_t)(j0 + pjj) * ROWS + tt * 32 + pb] = hn;
        }
        xg0 = xn0; xg1 = xn1; xg2 = xn2; xg3 = xn3;

        __syncthreads();
        if (tid == 0) {
            red_release_add(&d_bar, 1);
            while (ld_acq(&d_bar) < NBLK * (tt + 1)) { }
        }
        __syncthreads();
    }
}

// ======================================================================
extern "C" void kernel_launch(void* const* d_in, const int* in_sizes, int n_in,
                              void* d_out, int out_size) {
    const float* traj      = (const float*)d_in[0];
    const float* gcn_w     = (const float*)d_in[1];
    const float* gcn_b     = (const float*)d_in[2];
    const float* in_proj_w = (const float*)d_in[3];
    const float* in_proj_b = (const float*)d_in[4];
    const float* out_proj_w= (const float*)d_in[5];
    const float* out_proj_b= (const float*)d_in[6];
    // d_in[7]=va_w, d_in[8]=va_b : unused (uniform softmaxes)
    const float* w_ih      = (const float*)d_in[9];
    const float* w_hh      = (const float*)d_in[10];
    const float* b_ih      = (const float*)d_in[11];
    const float* b_hh      = (const float*)d_in[12];
    const float* lin1_w    = (const float*)d_in[13];
    const float* lin1_b    = (const float*)d_in[14];
    const float* lin2_w    = (const float*)d_in[15];
    const float* lin2_b    = (const float*)d_in[16];
    float* out = (float*)d_out;

    float *pG, *pPk, *pF1, *pWbig, *pbatt, *pbihh, *pXT, *pLT, *pH1;
    cudaGetSymbolAddress((void**)&pG,    d_G);
    cudaGetSymbolAddress((void**)&pPk,   d_Pk);
    cudaGetSymbolAddress((void**)&pF1,   d_F1);
    cudaGetSymbolAddress((void**)&pWbig, d_Wbig);
    cudaGetSymbolAddress((void**)&pbatt, d_batt);
    cudaGetSymbolAddress((void**)&pbihh, d_bihh);
    cudaGetSymbolAddress((void**)&pXT,   d_XT);
    cudaGetSymbolAddress((void**)&pLT,   d_LT);
    cudaGetSymbolAddress((void**)&pH1,   d_H1);

    const float* bv = in_proj_b + 2 * D_;
    const float* Wv = in_proj_w + (size_t)2 * D_ * D_;
    const int KQ = D_ / 4;                // 64 per split-K=4 part

    k_init<<<ROWS, 256>>>(traj, gcn_w, gcn_b);

    k_gemv<<<32, 256>>>(out_proj_w, D_, bv, out_proj_b, nullptr, pbatt, D_);
    k_gemv<<<256, 256>>>(w_ih, D_, pbatt, b_ih, b_hh, pbihh, G4);

    // F1 = w_ih @ Wop   (fp32 scalar split-K=4 — exact)
    sgemm_fold<<<dim3(D_ / 128, G4 / 64, 4), 256>>>(
        w_ih, out_proj_w, pPk, G4, D_, KQ, D_, D_,
        (size_t)KQ, (size_t)KQ * D_);
    k_addn<<<(G4 * D_ / 4 + 255) / 256, 256>>>(pPk, pF1, G4 * D_ / 4, 4);

    // Wbig = F1 @ Wv    (fp32 scalar split-K=4 — exact)
    sgemm_fold<<<dim3(D_ / 128, G4 / 64, 4), 256>>>(
        pF1, Wv, pPk, G4, D_, KQ, D_, D_,
        (size_t)KQ, (size_t)KQ * D_);
    k_addn<<<(G4 * D_ / 4 + 255) / 256, 256>>>(pPk, pWbig, G4 * D_ / 4, 4);

    // XT = Wbig @ G^T + bias_x[m]   (tf32)
    tf32gemm<0, 0, 1, 0, 0><<<dim3(ROWS / 128, G4 / 128), 256>>>(
        pWbig, pG, pbihh, pXT, G4, ROWS, D_, D_, D_);

    // persistent LSTM (tensor-core, compensated weights)
    k_lstm<<<NBLK, 256>>>(w_hh);

    // H1 = relu(L @ lin1_w^T + b)   (tf32, A = LT k-major)
    tf32gemm<1, 0, 2, 1, 0><<<dim3(D_ / 128, ROWS / 128), 256>>>(
        pLT, lin1_w, lin1_b, pH1, ROWS, D_, LH, ROWS, LH);

    // out = H1 @ lin2_w^T + b       (tf32, permuted rows)
    tf32gemm<0, 0, 2, 0, 1><<<dim3(128 / 128, ROWS / 128), 256>>>(
        pH1, lin2_w, lin2_b, out, ROWS, 128, D_, D_, D_);
}